// round 4
// baseline (speedup 1.0000x reference)
#include <cuda_runtime.h>
#include <cstdint>

// ---------------------------------------------------------------------------
// LightGCN: final = 0.25*(E0 + L1 + L2 + L3), Lk = A @ L(k-1)  (A: 10M COO edges)
// Outputs (6 x [16384,64] f32, concatenated):
//   users_emb, pos_emb, neg_emb  (rows of `final`)
//   users_ego, pos_ego, neg_ego  (rows of raw embeddings)
// ---------------------------------------------------------------------------

#define N_USERS 100000
#define N_ITEMS 50000
#define N_NODES 150000
#define EMB     64
#define VEC     16          // EMB/4 float4 per row
#define BATCH   16384
#define BITMAP_WORDS ((N_NODES + 31) / 32)

// Scratch (graph-capture safe: static __device__ globals, no allocs)
__device__ float4 g_l1[N_NODES * VEC];
__device__ float4 g_l2[N_NODES * VEC];
__device__ float4 g_l3[N_NODES * VEC];
__device__ unsigned int g_bitmap[BITMAP_WORDS];

// ---------------------------------------------------------------------------
// Zero all scratch (atomic targets must start at 0 every call)
// ---------------------------------------------------------------------------
__global__ __launch_bounds__(256)
void zero_scratch() {
    const int total = N_NODES * VEC;           // per buffer: 2.4M float4
    const float4 z = {0.f, 0.f, 0.f, 0.f};
    for (int i = blockIdx.x * blockDim.x + threadIdx.x; i < total;
         i += gridDim.x * blockDim.x) {
        g_l1[i] = z;
        g_l2[i] = z;
        g_l3[i] = z;
    }
    int t = blockIdx.x * blockDim.x + threadIdx.x;
    if (t < BITMAP_WORDS) g_bitmap[t] = 0u;
}

// ---------------------------------------------------------------------------
// Mark rows that the final gather will actually read (users + items+offset)
// ---------------------------------------------------------------------------
__global__ __launch_bounds__(256)
void set_bitmap(const int* __restrict__ users,
                const int* __restrict__ pos,
                const int* __restrict__ neg) {
    int i = blockIdx.x * blockDim.x + threadIdx.x;
    int node = -1;
    if (i < BATCH)              node = users[i];
    else if (i < 2 * BATCH)     node = N_USERS + pos[i - BATCH];
    else if (i < 3 * BATCH)     node = N_USERS + neg[i - 2 * BATCH];
    if (node >= 0 && node < N_NODES)
        atomicOr(&g_bitmap[node >> 5], 1u << (node & 31));
}

// ---------------------------------------------------------------------------
// SpMM: y[row] += val * x[col]   (16 threads per edge, one float4 each)
// MODE 0: x = concat(user_emb, item_emb) -> g_l1
// MODE 1: x = g_l1 -> g_l2
// MODE 2: x = g_l2 -> g_l3, edges filtered by row-bitmap (only gathered rows)
// ---------------------------------------------------------------------------
template <int MODE>
__global__ __launch_bounds__(256)
void spmm_kernel(const int*   __restrict__ rows,
                 const int*   __restrict__ cols,
                 const float* __restrict__ vals,
                 const float4* __restrict__ user_emb,
                 const float4* __restrict__ item_emb,
                 int n_edges) {
    int gid = blockIdx.x * blockDim.x + threadIdx.x;
    int e = gid >> 4;
    int c = gid & 15;
    if (e >= n_edges) return;

    // streaming (evict-first) loads: keep node tables resident in L2
    int r = __ldcs(rows + e);
    if ((unsigned)r >= (unsigned)N_NODES) return;   // defensive

    if (MODE == 2) {
        // skip edges whose destination row is never read (~73% skipped)
        unsigned w = __ldg(&g_bitmap[r >> 5]);
        if (!((w >> (r & 31)) & 1u)) return;
    }

    int   col = __ldcs(cols + e);
    if ((unsigned)col >= (unsigned)N_NODES) return; // defensive
    float v   = __ldcs(vals + e);

    float4 xv;
    if (MODE == 0) {
        xv = (col < N_USERS) ? user_emb[col * VEC + c]
                             : item_emb[(col - N_USERS) * VEC + c];
    } else if (MODE == 1) {
        xv = g_l1[col * VEC + c];
    } else {
        xv = g_l2[col * VEC + c];
    }

    float4* dst;
    if (MODE == 0)      dst = &g_l1[r * VEC + c];
    else if (MODE == 1) dst = &g_l2[r * VEC + c];
    else                dst = &g_l3[r * VEC + c];

    float mx = v * xv.x, my = v * xv.y, mz = v * xv.z, mw = v * xv.w;
    asm volatile("red.global.add.v4.f32 [%0], {%1, %2, %3, %4};"
                 :: "l"(dst), "f"(mx), "f"(my), "f"(mz), "f"(mw)
                 : "memory");
}

// ---------------------------------------------------------------------------
// Final gather: compute 0.25*(ego + L1 + L2 + L3) only at the 3*BATCH
// requested rows, plus the three raw-embedding gathers.
// out layout: [6][BATCH][EMB] f32 contiguous.
// ---------------------------------------------------------------------------
__global__ __launch_bounds__(256)
void gather_kernel(const int* __restrict__ users,
                   const int* __restrict__ pos,
                   const int* __restrict__ neg,
                   const float4* __restrict__ user_emb,
                   const float4* __restrict__ item_emb,
                   float4* __restrict__ out) {
    int gid = blockIdx.x * blockDim.x + threadIdx.x;
    int i = gid >> 4;
    int c = gid & 15;
    if (i >= BATCH) return;

    int u = users[i];
    int p = pos[i];
    int n = neg[i];
    int un = u;
    int pn = N_USERS + p;
    int nn = N_USERS + n;

    const float a = 0.25f;

    float4 ue = user_emb[u * VEC + c];
    float4 pe = item_emb[p * VEC + c];
    float4 ne = item_emb[n * VEC + c];

    float4 l1u = g_l1[un * VEC + c], l2u = g_l2[un * VEC + c], l3u = g_l3[un * VEC + c];
    float4 l1p = g_l1[pn * VEC + c], l2p = g_l2[pn * VEC + c], l3p = g_l3[pn * VEC + c];
    float4 l1n = g_l1[nn * VEC + c], l2n = g_l2[nn * VEC + c], l3n = g_l3[nn * VEC + c];

    float4 fu, fp, fn;
    fu.x = a * (ue.x + l1u.x + l2u.x + l3u.x);
    fu.y = a * (ue.y + l1u.y + l2u.y + l3u.y);
    fu.z = a * (ue.z + l1u.z + l2u.z + l3u.z);
    fu.w = a * (ue.w + l1u.w + l2u.w + l3u.w);
    fp.x = a * (pe.x + l1p.x + l2p.x + l3p.x);
    fp.y = a * (pe.y + l1p.y + l2p.y + l3p.y);
    fp.z = a * (pe.z + l1p.z + l2p.z + l3p.z);
    fp.w = a * (pe.w + l1p.w + l2p.w + l3p.w);
    fn.x = a * (ne.x + l1n.x + l2n.x + l3n.x);
    fn.y = a * (ne.y + l1n.y + l2n.y + l3n.y);
    fn.z = a * (ne.z + l1n.z + l2n.z + l3n.z);
    fn.w = a * (ne.w + l1n.w + l2n.w + l3n.w);

    out[(0 * BATCH + i) * VEC + c] = fu;
    out[(1 * BATCH + i) * VEC + c] = fp;
    out[(2 * BATCH + i) * VEC + c] = fn;
    out[(3 * BATCH + i) * VEC + c] = ue;
    out[(4 * BATCH + i) * VEC + c] = pe;
    out[(5 * BATCH + i) * VEC + c] = ne;
}

// ---------------------------------------------------------------------------
extern "C" void kernel_launch(void* const* d_in, const int* in_sizes, int n_in,
                              void* d_out, int out_size) {
    const int*    adj_rows = (const int*)   d_in[0];
    const int*    adj_cols = (const int*)   d_in[1];
    const float*  adj_vals = (const float*) d_in[2];
    const int*    users    = (const int*)   d_in[3];
    const int*    pos      = (const int*)   d_in[4];
    const int*    neg      = (const int*)   d_in[5];
    const float4* user_emb = (const float4*)d_in[6];
    const float4* item_emb = (const float4*)d_in[7];
    float4*       out      = (float4*)      d_out;

    int n_edges = in_sizes[0];

    const int TPB = 256;

    // 1) zero scratch + bitmap
    zero_scratch<<<4096, TPB>>>();

    // 2) mark gathered rows
    set_bitmap<<<(3 * BATCH + TPB - 1) / TPB, TPB>>>(users, pos, neg);

    // 3) three propagation layers
    long long thr = (long long)n_edges * 16;
    int grid = (int)((thr + TPB - 1) / TPB);
    spmm_kernel<0><<<grid, TPB>>>(adj_rows, adj_cols, adj_vals, user_emb, item_emb, n_edges);
    spmm_kernel<1><<<grid, TPB>>>(adj_rows, adj_cols, adj_vals, user_emb, item_emb, n_edges);
    spmm_kernel<2><<<grid, TPB>>>(adj_rows, adj_cols, adj_vals, user_emb, item_emb, n_edges);

    // 4) gather outputs
    int gthr = BATCH * 16;
    gather_kernel<<<(gthr + TPB - 1) / TPB, TPB>>>(users, pos, neg, user_emb, item_emb, out);
}

// round 5
// speedup vs baseline: 2.8265x; 2.8265x over previous
#include <cuda_runtime.h>
#include <cstdint>

// ---------------------------------------------------------------------------
// LightGCN via per-call CSR build (no fp atomics in the SpMM layers).
//   final = 0.25*(E0 + L1 + L2 + L3),  Lk = A @ L(k-1),  A: 10M COO edges
// Outputs (6 x [16384,64] f32, concatenated):
//   users_emb, pos_emb, neg_emb  (rows of `final`)
//   users_ego, pos_ego, neg_ego  (rows of raw embeddings)
// ---------------------------------------------------------------------------

#define N_USERS 100000
#define N_ITEMS 50000
#define N_NODES 150000
#define EMB     64
#define VEC     16          // EMB/4 float4 per row
#define BATCH   16384
#define N_EDGES_MAX 10000000
#define BITMAP_WORDS ((N_NODES + 31) / 32)
#define SCAN_T  1024

// Scratch (graph-capture safe: static __device__ globals, no allocs)
__device__ float4 g_x0[N_NODES * VEC];     // concat(user_emb, item_emb)
__device__ float4 g_l1[N_NODES * VEC];
__device__ float4 g_l2[N_NODES * VEC];
__device__ float4 g_l3[N_NODES * VEC];
__device__ int2   g_csr[N_EDGES_MAX];      // (col, val-bits) per edge, row-grouped
__device__ int    g_count[N_NODES];
__device__ int    g_rowptr[N_NODES + 1];
__device__ int    g_cursor[N_NODES];
__device__ unsigned int g_bitmap[BITMAP_WORDS];

// ---------------------------------------------------------------------------
// Zero per-call metadata (counts + bitmap). Embedding buffers need NO zeroing:
// every row the gather reads is fully overwritten by a plain store.
// ---------------------------------------------------------------------------
__global__ __launch_bounds__(256)
void zero_meta() {
    for (int i = blockIdx.x * blockDim.x + threadIdx.x; i < N_NODES;
         i += gridDim.x * blockDim.x)
        g_count[i] = 0;
    int t = blockIdx.x * blockDim.x + threadIdx.x;
    if (t < BITMAP_WORDS) g_bitmap[t] = 0u;
}

// ---------------------------------------------------------------------------
// Mark rows that the final gather will actually read
// ---------------------------------------------------------------------------
__global__ __launch_bounds__(256)
void set_bitmap(const int* __restrict__ users,
                const int* __restrict__ pos,
                const int* __restrict__ neg) {
    int i = blockIdx.x * blockDim.x + threadIdx.x;
    int node = -1;
    if (i < BATCH)              node = users[i];
    else if (i < 2 * BATCH)     node = N_USERS + pos[i - BATCH];
    else if (i < 3 * BATCH)     node = N_USERS + neg[i - 2 * BATCH];
    if (node >= 0 && node < N_NODES)
        atomicOr(&g_bitmap[node >> 5], 1u << (node & 31));
}

// ---------------------------------------------------------------------------
// Row histogram (int RED, no return). 4 edges per thread via int4.
// ---------------------------------------------------------------------------
__global__ __launch_bounds__(256)
void histogram(const int* __restrict__ rows, int n) {
    int i = blockIdx.x * blockDim.x + threadIdx.x;
    int n4 = n >> 2;
    if (i < n4) {
        int4 r = __ldcs((const int4*)rows + i);
        if ((unsigned)r.x < (unsigned)N_NODES) atomicAdd(&g_count[r.x], 1);
        if ((unsigned)r.y < (unsigned)N_NODES) atomicAdd(&g_count[r.y], 1);
        if ((unsigned)r.z < (unsigned)N_NODES) atomicAdd(&g_count[r.z], 1);
        if ((unsigned)r.w < (unsigned)N_NODES) atomicAdd(&g_count[r.w], 1);
    }
    if (i < (n & 3)) {
        int r = rows[n4 * 4 + i];
        if ((unsigned)r < (unsigned)N_NODES) atomicAdd(&g_count[r], 1);
    }
}

// ---------------------------------------------------------------------------
// Single-block exclusive scan of g_count -> g_rowptr (and g_cursor copy).
// 1024 threads, each owns a contiguous chunk of ~147 rows.
// ---------------------------------------------------------------------------
__global__ __launch_bounds__(SCAN_T)
void scan_counts() {
    __shared__ int ssum[SCAN_T];
    const int CH = (N_NODES + SCAN_T - 1) / SCAN_T;
    int t = threadIdx.x;
    int base = t * CH;

    int s = 0;
    for (int i = 0; i < CH; i++) {
        int idx = base + i;
        if (idx < N_NODES) s += g_count[idx];
    }
    ssum[t] = s;
    __syncthreads();

    // inclusive scan (Hillis-Steele, read-then-sync-then-write)
    for (int off = 1; off < SCAN_T; off <<= 1) {
        int v = (t >= off) ? ssum[t - off] : 0;
        __syncthreads();
        ssum[t] += v;
        __syncthreads();
    }
    int run = (t == 0) ? 0 : ssum[t - 1];   // exclusive prefix of my chunk

    for (int i = 0; i < CH; i++) {
        int idx = base + i;
        if (idx < N_NODES) {
            int c = g_count[idx];
            g_rowptr[idx] = run;
            g_cursor[idx] = run;
            run += c;
        }
    }
    if (t == SCAN_T - 1) g_rowptr[N_NODES] = run;
}

// ---------------------------------------------------------------------------
// Scatter edges into CSR order (atomic cursor per row; order within a row is
// arbitrary — fp sums reordered, within 1e-3 tolerance by a wide margin).
// ---------------------------------------------------------------------------
__global__ __launch_bounds__(256)
void scatter_csr(const int* __restrict__ rows,
                 const int* __restrict__ cols,
                 const float* __restrict__ vals, int n) {
    int e = blockIdx.x * blockDim.x + threadIdx.x;
    if (e >= n) return;
    int r = __ldcs(rows + e);
    if ((unsigned)r >= (unsigned)N_NODES) return;
    int c = __ldcs(cols + e);
    if ((unsigned)c >= (unsigned)N_NODES) return;
    float v = __ldcs(vals + e);
    int pos = atomicAdd(&g_cursor[r], 1);
    if ((unsigned)pos < (unsigned)N_EDGES_MAX)
        g_csr[pos] = make_int2(c, __float_as_int(v));
}

// ---------------------------------------------------------------------------
// Build x0 = concat(user_emb, item_emb)
// ---------------------------------------------------------------------------
__global__ __launch_bounds__(256)
void copy_x0(const float4* __restrict__ user_emb,
             const float4* __restrict__ item_emb) {
    const int total = N_NODES * VEC;
    for (int i = blockIdx.x * blockDim.x + threadIdx.x; i < total;
         i += gridDim.x * blockDim.x) {
        g_x0[i] = (i < N_USERS * VEC) ? user_emb[i]
                                      : item_emb[i - N_USERS * VEC];
    }
}

// ---------------------------------------------------------------------------
// CSR SpMM: y[row] = sum_j val_j * x[col_j].  16 threads per row, one float4
// column each; register accumulation; ONE plain store per lane. No atomics.
// FILTER=1: compute only rows the gather reads (~27% of rows).
// ---------------------------------------------------------------------------
template <int FILTER>
__global__ __launch_bounds__(256)
void spmm_csr(const float4* __restrict__ x, float4* __restrict__ y) {
    int gid = blockIdx.x * blockDim.x + threadIdx.x;
    int row = gid >> 4;
    int c   = gid & 15;
    if (row >= N_NODES) return;
    if (FILTER) {
        if (!((g_bitmap[row >> 5] >> (row & 31)) & 1u)) return;
    }

    int beg = g_rowptr[row];
    int end = g_rowptr[row + 1];

    float4 acc = {0.f, 0.f, 0.f, 0.f};
    // __ldcs on CSR stream: evict-first so the 38MB x table stays L2-resident
    #pragma unroll 4
    for (int j = beg; j < end; j++) {
        int2  cv = __ldcs(&g_csr[j]);
        float v  = __int_as_float(cv.y);
        float4 xv = x[(size_t)cv.x * VEC + c];
        acc.x = fmaf(v, xv.x, acc.x);
        acc.y = fmaf(v, xv.y, acc.y);
        acc.z = fmaf(v, xv.z, acc.z);
        acc.w = fmaf(v, xv.w, acc.w);
    }
    y[(size_t)row * VEC + c] = acc;
}

// ---------------------------------------------------------------------------
// Final gather: 0.25*(ego + L1 + L2 + L3) at the requested rows + raw gathers.
// out layout: [6][BATCH][EMB] f32 contiguous.
// ---------------------------------------------------------------------------
__global__ __launch_bounds__(256)
void gather_kernel(const int* __restrict__ users,
                   const int* __restrict__ pos,
                   const int* __restrict__ neg,
                   const float4* __restrict__ user_emb,
                   const float4* __restrict__ item_emb,
                   float4* __restrict__ out) {
    int gid = blockIdx.x * blockDim.x + threadIdx.x;
    int i = gid >> 4;
    int c = gid & 15;
    if (i >= BATCH) return;

    int u = users[i];
    int p = pos[i];
    int n = neg[i];
    int un = u;
    int pn = N_USERS + p;
    int nn = N_USERS + n;

    const float a = 0.25f;

    float4 ue = user_emb[u * VEC + c];
    float4 pe = item_emb[p * VEC + c];
    float4 ne = item_emb[n * VEC + c];

    float4 l1u = g_l1[un * VEC + c], l2u = g_l2[un * VEC + c], l3u = g_l3[un * VEC + c];
    float4 l1p = g_l1[pn * VEC + c], l2p = g_l2[pn * VEC + c], l3p = g_l3[pn * VEC + c];
    float4 l1n = g_l1[nn * VEC + c], l2n = g_l2[nn * VEC + c], l3n = g_l3[nn * VEC + c];

    float4 fu, fp, fn;
    fu.x = a * (ue.x + l1u.x + l2u.x + l3u.x);
    fu.y = a * (ue.y + l1u.y + l2u.y + l3u.y);
    fu.z = a * (ue.z + l1u.z + l2u.z + l3u.z);
    fu.w = a * (ue.w + l1u.w + l2u.w + l3u.w);
    fp.x = a * (pe.x + l1p.x + l2p.x + l3p.x);
    fp.y = a * (pe.y + l1p.y + l2p.y + l3p.y);
    fp.z = a * (pe.z + l1p.z + l2p.z + l3p.z);
    fp.w = a * (pe.w + l1p.w + l2p.w + l3p.w);
    fn.x = a * (ne.x + l1n.x + l2n.x + l3n.x);
    fn.y = a * (ne.y + l1n.y + l2n.y + l3n.y);
    fn.z = a * (ne.z + l1n.z + l2n.z + l3n.z);
    fn.w = a * (ne.w + l1n.w + l2n.w + l3n.w);

    out[(0 * BATCH + i) * VEC + c] = fu;
    out[(1 * BATCH + i) * VEC + c] = fp;
    out[(2 * BATCH + i) * VEC + c] = fn;
    out[(3 * BATCH + i) * VEC + c] = ue;
    out[(4 * BATCH + i) * VEC + c] = pe;
    out[(5 * BATCH + i) * VEC + c] = ne;
}

// ---------------------------------------------------------------------------
extern "C" void kernel_launch(void* const* d_in, const int* in_sizes, int n_in,
                              void* d_out, int out_size) {
    const int*    adj_rows = (const int*)   d_in[0];
    const int*    adj_cols = (const int*)   d_in[1];
    const float*  adj_vals = (const float*) d_in[2];
    const int*    users    = (const int*)   d_in[3];
    const int*    pos      = (const int*)   d_in[4];
    const int*    neg      = (const int*)   d_in[5];
    const float4* user_emb = (const float4*)d_in[6];
    const float4* item_emb = (const float4*)d_in[7];
    float4*       out      = (float4*)      d_out;

    int n_edges = in_sizes[0];
    if (n_edges > N_EDGES_MAX) n_edges = N_EDGES_MAX;

    const int TPB = 256;

    // metadata
    zero_meta<<<(N_NODES + TPB - 1) / TPB, TPB>>>();
    set_bitmap<<<(3 * BATCH + TPB - 1) / TPB, TPB>>>(users, pos, neg);

    // CSR build
    int hgrid = ((n_edges >> 2) + TPB - 1) / TPB + 1;
    histogram<<<hgrid, TPB>>>(adj_rows, n_edges);
    scan_counts<<<1, SCAN_T>>>();
    scatter_csr<<<(n_edges + TPB - 1) / TPB, TPB>>>(adj_rows, adj_cols, adj_vals, n_edges);

    // x0 concat
    copy_x0<<<2048, TPB>>>(user_emb, item_emb);

    // three propagation layers, atomic-free
    // device-pointer addresses of __device__ globals are usable directly in kernels;
    // pass via small launcher lambdas using the symbols inside the kernels instead:
    {
        int sgrid = (N_NODES * VEC + TPB - 1) / TPB;
        // need raw pointers to device globals for x/y args: obtain via kernels that
        // reference symbols directly is cleaner, but passing works via cudaGetSymbolAddress
        // which is not graph-capture-hostile (host-side, done every call, no alloc).
        void* px0; void* pl1; void* pl2; void* pl3;
        cudaGetSymbolAddress(&px0, g_x0);
        cudaGetSymbolAddress(&pl1, g_l1);
        cudaGetSymbolAddress(&pl2, g_l2);
        cudaGetSymbolAddress(&pl3, g_l3);
        spmm_csr<0><<<sgrid, TPB>>>((const float4*)px0, (float4*)pl1);
        spmm_csr<0><<<sgrid, TPB>>>((const float4*)pl1, (float4*)pl2);
        spmm_csr<1><<<sgrid, TPB>>>((const float4*)pl2, (float4*)pl3);
    }

    // outputs
    gather_kernel<<<(BATCH * VEC + TPB - 1) / TPB, TPB>>>(users, pos, neg,
                                                          user_emb, item_emb, out);
}

// round 6
// speedup vs baseline: 3.8204x; 1.3516x over previous
#include <cuda_runtime.h>
#include <cstdint>

// ---------------------------------------------------------------------------
// LightGCN via per-call CSR build (no fp atomics in the SpMM layers).
//   final = 0.25*(E0 + L1 + L2 + L3),  Lk = A @ L(k-1),  A: 10M COO edges
// Outputs (6 x [16384,64] f32, concatenated):
//   users_emb, pos_emb, neg_emb  (rows of `final`)
//   users_ego, pos_ego, neg_ego  (rows of raw embeddings)
// ---------------------------------------------------------------------------

#define N_USERS 100000
#define N_ITEMS 50000
#define N_NODES 150000
#define EMB     64
#define VEC     16          // EMB/4 float4 per row
#define BATCH   16384
#define N_EDGES_MAX 10000000
#define BITMAP_WORDS ((N_NODES + 31) / 32)

#define SCAN_BT   1024                               // threads per scan block
#define SCAN_NB   ((N_NODES + SCAN_BT - 1) / SCAN_BT) // 147 blocks

// Scratch (graph-capture safe: static __device__ globals, no allocs)
__device__ float4 g_x0[N_NODES * VEC];     // concat(user_emb, item_emb)
__device__ float4 g_l1[N_NODES * VEC];
__device__ float4 g_l2[N_NODES * VEC];
__device__ float4 g_l3[N_NODES * VEC];
__device__ int2   g_csr[N_EDGES_MAX];      // (col, val-bits) per edge, row-grouped
__device__ int    g_count[N_NODES];
__device__ int    g_tmp[N_NODES];          // block-local exclusive prefix
__device__ int    g_bsum[SCAN_NB];         // per-block totals
__device__ int    g_boff[SCAN_NB];         // exclusive block offsets
__device__ int    g_rowptr[N_NODES + 1];
__device__ int    g_cursor[N_NODES];
__device__ unsigned int g_bitmap[BITMAP_WORDS];

// ---------------------------------------------------------------------------
// Zero per-call metadata (counts + bitmap). Embedding buffers need NO zeroing:
// every row the gather reads is fully overwritten by a plain store.
// ---------------------------------------------------------------------------
__global__ __launch_bounds__(256)
void zero_meta() {
    for (int i = blockIdx.x * blockDim.x + threadIdx.x; i < N_NODES;
         i += gridDim.x * blockDim.x)
        g_count[i] = 0;
    int t = blockIdx.x * blockDim.x + threadIdx.x;
    if (t < BITMAP_WORDS) g_bitmap[t] = 0u;
}

// ---------------------------------------------------------------------------
// Mark rows that the final gather will actually read
// ---------------------------------------------------------------------------
__global__ __launch_bounds__(256)
void set_bitmap(const int* __restrict__ users,
                const int* __restrict__ pos,
                const int* __restrict__ neg) {
    int i = blockIdx.x * blockDim.x + threadIdx.x;
    int node = -1;
    if (i < BATCH)              node = users[i];
    else if (i < 2 * BATCH)     node = N_USERS + pos[i - BATCH];
    else if (i < 3 * BATCH)     node = N_USERS + neg[i - 2 * BATCH];
    if (node >= 0 && node < N_NODES)
        atomicOr(&g_bitmap[node >> 5], 1u << (node & 31));
}

// ---------------------------------------------------------------------------
// Row histogram (int RED, no return). 4 edges per thread via int4.
// ---------------------------------------------------------------------------
__global__ __launch_bounds__(256)
void histogram(const int* __restrict__ rows, int n) {
    int i = blockIdx.x * blockDim.x + threadIdx.x;
    int n4 = n >> 2;
    if (i < n4) {
        int4 r = __ldcs((const int4*)rows + i);
        if ((unsigned)r.x < (unsigned)N_NODES) atomicAdd(&g_count[r.x], 1);
        if ((unsigned)r.y < (unsigned)N_NODES) atomicAdd(&g_count[r.y], 1);
        if ((unsigned)r.z < (unsigned)N_NODES) atomicAdd(&g_count[r.z], 1);
        if ((unsigned)r.w < (unsigned)N_NODES) atomicAdd(&g_count[r.w], 1);
    }
    if (i < (n & 3)) {
        int r = rows[n4 * 4 + i];
        if ((unsigned)r < (unsigned)N_NODES) atomicAdd(&g_count[r], 1);
    }
}

// ---------------------------------------------------------------------------
// Parallel 3-pass scan of g_count -> g_rowptr (+ g_cursor).
// Pass 1: per-block (1024-wide) inclusive scan; store block-local exclusive
//         prefix to g_tmp and block total to g_bsum.
// ---------------------------------------------------------------------------
__global__ __launch_bounds__(SCAN_BT)
void scan_pass1() {
    __shared__ int s[SCAN_BT];
    int t = threadIdx.x;
    int idx = blockIdx.x * SCAN_BT + t;
    int v = (idx < N_NODES) ? g_count[idx] : 0;
    s[t] = v;
    __syncthreads();
    #pragma unroll
    for (int off = 1; off < SCAN_BT; off <<= 1) {
        int u = (t >= off) ? s[t - off] : 0;
        __syncthreads();
        s[t] += u;
        __syncthreads();
    }
    if (idx < N_NODES) g_tmp[idx] = s[t] - v;      // exclusive within block
    if (t == SCAN_BT - 1) g_bsum[blockIdx.x] = s[t];
}

// Pass 2: one small block scans the 147 block totals (exclusive) -> g_boff,
//         writes grand total to g_rowptr[N_NODES].
__global__ __launch_bounds__(256)
void scan_pass2() {
    __shared__ int s[256];
    int t = threadIdx.x;
    int v = (t < SCAN_NB) ? g_bsum[t] : 0;
    s[t] = v;
    __syncthreads();
    #pragma unroll
    for (int off = 1; off < 256; off <<= 1) {
        int u = (t >= off) ? s[t - off] : 0;
        __syncthreads();
        s[t] += u;
        __syncthreads();
    }
    if (t < SCAN_NB) g_boff[t] = s[t] - v;         // exclusive
    if (t == 255) g_rowptr[N_NODES] = s[t];
}

// Pass 3: add block offset; emit rowptr + cursor.
__global__ __launch_bounds__(256)
void scan_pass3() {
    int idx = blockIdx.x * blockDim.x + threadIdx.x;
    if (idx < N_NODES) {
        int v = g_tmp[idx] + g_boff[idx / SCAN_BT];
        g_rowptr[idx] = v;
        g_cursor[idx] = v;
    }
}

// ---------------------------------------------------------------------------
// Scatter edges into CSR order (atomic cursor per row; order within a row is
// arbitrary — fp sums reordered, within 1e-3 tolerance by a wide margin).
// ---------------------------------------------------------------------------
__global__ __launch_bounds__(256)
void scatter_csr(const int* __restrict__ rows,
                 const int* __restrict__ cols,
                 const float* __restrict__ vals, int n) {
    int e = blockIdx.x * blockDim.x + threadIdx.x;
    if (e >= n) return;
    int r = __ldcs(rows + e);
    if ((unsigned)r >= (unsigned)N_NODES) return;
    int c = __ldcs(cols + e);
    if ((unsigned)c >= (unsigned)N_NODES) return;
    float v = __ldcs(vals + e);
    int pos = atomicAdd(&g_cursor[r], 1);
    if ((unsigned)pos < (unsigned)N_EDGES_MAX)
        g_csr[pos] = make_int2(c, __float_as_int(v));
}

// ---------------------------------------------------------------------------
// Build x0 = concat(user_emb, item_emb)
// ---------------------------------------------------------------------------
__global__ __launch_bounds__(256)
void copy_x0(const float4* __restrict__ user_emb,
             const float4* __restrict__ item_emb) {
    const int total = N_NODES * VEC;
    for (int i = blockIdx.x * blockDim.x + threadIdx.x; i < total;
         i += gridDim.x * blockDim.x) {
        g_x0[i] = (i < N_USERS * VEC) ? user_emb[i]
                                      : item_emb[i - N_USERS * VEC];
    }
}

// ---------------------------------------------------------------------------
// CSR SpMM: y[row] = sum_j val_j * x[col_j].  16 threads per row, one float4
// column each; register accumulation; ONE plain store per lane. No atomics.
// FILTER=1: compute only rows the gather reads (~27% of rows).
// ---------------------------------------------------------------------------
template <int FILTER>
__global__ __launch_bounds__(256)
void spmm_csr(const float4* __restrict__ x, float4* __restrict__ y) {
    int gid = blockIdx.x * blockDim.x + threadIdx.x;
    int row = gid >> 4;
    int c   = gid & 15;
    if (row >= N_NODES) return;
    if (FILTER) {
        if (!((g_bitmap[row >> 5] >> (row & 31)) & 1u)) return;
    }

    int beg = g_rowptr[row];
    int end = g_rowptr[row + 1];

    float4 acc = {0.f, 0.f, 0.f, 0.f};
    // __ldcs on CSR stream: evict-first so the 38MB x table stays L2-resident
    #pragma unroll 4
    for (int j = beg; j < end; j++) {
        int2  cv = __ldcs(&g_csr[j]);
        float v  = __int_as_float(cv.y);
        float4 xv = x[(size_t)cv.x * VEC + c];
        acc.x = fmaf(v, xv.x, acc.x);
        acc.y = fmaf(v, xv.y, acc.y);
        acc.z = fmaf(v, xv.z, acc.z);
        acc.w = fmaf(v, xv.w, acc.w);
    }
    y[(size_t)row * VEC + c] = acc;
}

// ---------------------------------------------------------------------------
// Final gather: 0.25*(ego + L1 + L2 + L3) at the requested rows + raw gathers.
// out layout: [6][BATCH][EMB] f32 contiguous.
// ---------------------------------------------------------------------------
__global__ __launch_bounds__(256)
void gather_kernel(const int* __restrict__ users,
                   const int* __restrict__ pos,
                   const int* __restrict__ neg,
                   const float4* __restrict__ user_emb,
                   const float4* __restrict__ item_emb,
                   float4* __restrict__ out) {
    int gid = blockIdx.x * blockDim.x + threadIdx.x;
    int i = gid >> 4;
    int c = gid & 15;
    if (i >= BATCH) return;

    int u = users[i];
    int p = pos[i];
    int n = neg[i];
    int un = u;
    int pn = N_USERS + p;
    int nn = N_USERS + n;

    const float a = 0.25f;

    float4 ue = user_emb[u * VEC + c];
    float4 pe = item_emb[p * VEC + c];
    float4 ne = item_emb[n * VEC + c];

    float4 l1u = g_l1[un * VEC + c], l2u = g_l2[un * VEC + c], l3u = g_l3[un * VEC + c];
    float4 l1p = g_l1[pn * VEC + c], l2p = g_l2[pn * VEC + c], l3p = g_l3[pn * VEC + c];
    float4 l1n = g_l1[nn * VEC + c], l2n = g_l2[nn * VEC + c], l3n = g_l3[nn * VEC + c];

    float4 fu, fp, fn;
    fu.x = a * (ue.x + l1u.x + l2u.x + l3u.x);
    fu.y = a * (ue.y + l1u.y + l2u.y + l3u.y);
    fu.z = a * (ue.z + l1u.z + l2u.z + l3u.z);
    fu.w = a * (ue.w + l1u.w + l2u.w + l3u.w);
    fp.x = a * (pe.x + l1p.x + l2p.x + l3p.x);
    fp.y = a * (pe.y + l1p.y + l2p.y + l3p.y);
    fp.z = a * (pe.z + l1p.z + l2p.z + l3p.z);
    fp.w = a * (pe.w + l1p.w + l2p.w + l3p.w);
    fn.x = a * (ne.x + l1n.x + l2n.x + l3n.x);
    fn.y = a * (ne.y + l1n.y + l2n.y + l3n.y);
    fn.z = a * (ne.z + l1n.z + l2n.z + l3n.z);
    fn.w = a * (ne.w + l1n.w + l2n.w + l3n.w);

    out[(0 * BATCH + i) * VEC + c] = fu;
    out[(1 * BATCH + i) * VEC + c] = fp;
    out[(2 * BATCH + i) * VEC + c] = fn;
    out[(3 * BATCH + i) * VEC + c] = ue;
    out[(4 * BATCH + i) * VEC + c] = pe;
    out[(5 * BATCH + i) * VEC + c] = ne;
}

// ---------------------------------------------------------------------------
extern "C" void kernel_launch(void* const* d_in, const int* in_sizes, int n_in,
                              void* d_out, int out_size) {
    const int*    adj_rows = (const int*)   d_in[0];
    const int*    adj_cols = (const int*)   d_in[1];
    const float*  adj_vals = (const float*) d_in[2];
    const int*    users    = (const int*)   d_in[3];
    const int*    pos      = (const int*)   d_in[4];
    const int*    neg      = (const int*)   d_in[5];
    const float4* user_emb = (const float4*)d_in[6];
    const float4* item_emb = (const float4*)d_in[7];
    float4*       out      = (float4*)      d_out;

    int n_edges = in_sizes[0];
    if (n_edges > N_EDGES_MAX) n_edges = N_EDGES_MAX;

    const int TPB = 256;

    // metadata
    zero_meta<<<(N_NODES + TPB - 1) / TPB, TPB>>>();
    set_bitmap<<<(3 * BATCH + TPB - 1) / TPB, TPB>>>(users, pos, neg);

    // CSR build
    int hgrid = ((n_edges >> 2) + TPB - 1) / TPB + 1;
    histogram<<<hgrid, TPB>>>(adj_rows, n_edges);
    scan_pass1<<<SCAN_NB, SCAN_BT>>>();
    scan_pass2<<<1, 256>>>();
    scan_pass3<<<(N_NODES + TPB - 1) / TPB, TPB>>>();
    scatter_csr<<<(n_edges + TPB - 1) / TPB, TPB>>>(adj_rows, adj_cols, adj_vals, n_edges);

    // x0 concat
    copy_x0<<<2048, TPB>>>(user_emb, item_emb);

    // three propagation layers, atomic-free
    {
        int sgrid = (N_NODES * VEC + TPB - 1) / TPB;
        void* px0; void* pl1; void* pl2; void* pl3;
        cudaGetSymbolAddress(&px0, g_x0);
        cudaGetSymbolAddress(&pl1, g_l1);
        cudaGetSymbolAddress(&pl2, g_l2);
        cudaGetSymbolAddress(&pl3, g_l3);
        spmm_csr<0><<<sgrid, TPB>>>((const float4*)px0, (float4*)pl1);
        spmm_csr<0><<<sgrid, TPB>>>((const float4*)pl1, (float4*)pl2);
        spmm_csr<1><<<sgrid, TPB>>>((const float4*)pl2, (float4*)pl3);
    }

    // outputs
    gather_kernel<<<(BATCH * VEC + TPB - 1) / TPB, TPB>>>(users, pos, neg,
                                                          user_emb, item_emb, out);
}

// round 7
// speedup vs baseline: 4.4167x; 1.1561x over previous
#include <cuda_runtime.h>
#include <cuda_fp16.h>
#include <cstdint>

// ---------------------------------------------------------------------------
// LightGCN via per-call CSR build + fp16 intermediate storage.
//   final = 0.25*(E0 + L1 + L2 + L3),  Lk = A @ L(k-1),  A: 10M COO edges
// Intermediates (x0,L1,L2,L3) stored fp16 (f32 accumulation in registers);
// ego terms read from the original f32 embeddings, so only the propagated
// terms carry fp16 rounding (~1e-4 rel, vs 1e-3 tolerance).
// Outputs (6 x [16384,64] f32): users_emb,pos_emb,neg_emb,users_ego,pos_ego,neg_ego
// ---------------------------------------------------------------------------

#define N_USERS 100000
#define N_ITEMS 50000
#define N_NODES 150000
#define EMB     64
#define BATCH   16384
#define N_EDGES_MAX 10000000
#define BITMAP_WORDS ((N_NODES + 31) / 32)

#define ROW_U4  8    // 64 halfs per row = 8 uint4 (16B each)

#define SCAN_BT   1024
#define SCAN_NB   ((N_NODES + SCAN_BT - 1) / SCAN_BT)

// Scratch (graph-capture safe: static __device__ globals, no allocs)
__device__ uint4  g_x0h[N_NODES * ROW_U4];   // fp16 concat(user_emb, item_emb)
__device__ uint4  g_l1h[N_NODES * ROW_U4];
__device__ uint4  g_l2h[N_NODES * ROW_U4];
__device__ uint4  g_l3h[N_NODES * ROW_U4];
__device__ int2   g_csr[N_EDGES_MAX];        // (col, val-bits), row-grouped
__device__ int    g_count[N_NODES];
__device__ int    g_tmp[N_NODES];
__device__ int    g_bsum[SCAN_NB];
__device__ int    g_boff[SCAN_NB];
__device__ int    g_rowptr[N_NODES + 1];
__device__ int    g_cursor[N_NODES];
__device__ unsigned int g_bitmap[BITMAP_WORDS];

// --- fp16 pack/unpack helpers ---------------------------------------------
__device__ __forceinline__ float2 h2f(unsigned int u) {
    __half2 h = *reinterpret_cast<__half2*>(&u);
    return __half22float2(h);
}
__device__ __forceinline__ unsigned int f2h(float a, float b) {
    __half2 h = __floats2half2_rn(a, b);
    return *reinterpret_cast<unsigned int*>(&h);
}

// ---------------------------------------------------------------------------
__global__ __launch_bounds__(256)
void zero_meta() {
    for (int i = blockIdx.x * blockDim.x + threadIdx.x; i < N_NODES;
         i += gridDim.x * blockDim.x)
        g_count[i] = 0;
    int t = blockIdx.x * blockDim.x + threadIdx.x;
    if (t < BITMAP_WORDS) g_bitmap[t] = 0u;
}

__global__ __launch_bounds__(256)
void set_bitmap(const int* __restrict__ users,
                const int* __restrict__ pos,
                const int* __restrict__ neg) {
    int i = blockIdx.x * blockDim.x + threadIdx.x;
    int node = -1;
    if (i < BATCH)              node = users[i];
    else if (i < 2 * BATCH)     node = N_USERS + pos[i - BATCH];
    else if (i < 3 * BATCH)     node = N_USERS + neg[i - 2 * BATCH];
    if (node >= 0 && node < N_NODES)
        atomicOr(&g_bitmap[node >> 5], 1u << (node & 31));
}

// ---------------------------------------------------------------------------
// Row histogram (int RED), 4 edges per thread via int4.
// ---------------------------------------------------------------------------
__global__ __launch_bounds__(256)
void histogram(const int* __restrict__ rows, int n) {
    int i = blockIdx.x * blockDim.x + threadIdx.x;
    int n4 = n >> 2;
    if (i < n4) {
        int4 r = __ldcs((const int4*)rows + i);
        if ((unsigned)r.x < (unsigned)N_NODES) atomicAdd(&g_count[r.x], 1);
        if ((unsigned)r.y < (unsigned)N_NODES) atomicAdd(&g_count[r.y], 1);
        if ((unsigned)r.z < (unsigned)N_NODES) atomicAdd(&g_count[r.z], 1);
        if ((unsigned)r.w < (unsigned)N_NODES) atomicAdd(&g_count[r.w], 1);
    }
    if (i < (n & 3)) {
        int r = rows[n4 * 4 + i];
        if ((unsigned)r < (unsigned)N_NODES) atomicAdd(&g_count[r], 1);
    }
}

// ---------------------------------------------------------------------------
// Parallel 3-pass scan of g_count -> g_rowptr (+ g_cursor).
// ---------------------------------------------------------------------------
__global__ __launch_bounds__(SCAN_BT)
void scan_pass1() {
    __shared__ int s[SCAN_BT];
    int t = threadIdx.x;
    int idx = blockIdx.x * SCAN_BT + t;
    int v = (idx < N_NODES) ? g_count[idx] : 0;
    s[t] = v;
    __syncthreads();
    #pragma unroll
    for (int off = 1; off < SCAN_BT; off <<= 1) {
        int u = (t >= off) ? s[t - off] : 0;
        __syncthreads();
        s[t] += u;
        __syncthreads();
    }
    if (idx < N_NODES) g_tmp[idx] = s[t] - v;
    if (t == SCAN_BT - 1) g_bsum[blockIdx.x] = s[t];
}

__global__ __launch_bounds__(256)
void scan_pass2() {
    __shared__ int s[256];
    int t = threadIdx.x;
    int v = (t < SCAN_NB) ? g_bsum[t] : 0;
    s[t] = v;
    __syncthreads();
    #pragma unroll
    for (int off = 1; off < 256; off <<= 1) {
        int u = (t >= off) ? s[t - off] : 0;
        __syncthreads();
        s[t] += u;
        __syncthreads();
    }
    if (t < SCAN_NB) g_boff[t] = s[t] - v;
    if (t == 255) g_rowptr[N_NODES] = s[t];
}

__global__ __launch_bounds__(256)
void scan_pass3() {
    int idx = blockIdx.x * blockDim.x + threadIdx.x;
    if (idx < N_NODES) {
        int v = g_tmp[idx] + g_boff[idx / SCAN_BT];
        g_rowptr[idx] = v;
        g_cursor[idx] = v;
    }
}

// ---------------------------------------------------------------------------
// Scatter edges into CSR order (atomic row cursor; within-row order arbitrary).
// ---------------------------------------------------------------------------
__global__ __launch_bounds__(256)
void scatter_csr(const int* __restrict__ rows,
                 const int* __restrict__ cols,
                 const float* __restrict__ vals, int n) {
    int e = blockIdx.x * blockDim.x + threadIdx.x;
    if (e >= n) return;
    int r = __ldcs(rows + e);
    if ((unsigned)r >= (unsigned)N_NODES) return;
    int c = __ldcs(cols + e);
    if ((unsigned)c >= (unsigned)N_NODES) return;
    float v = __ldcs(vals + e);
    int pos = atomicAdd(&g_cursor[r], 1);
    if ((unsigned)pos < (unsigned)N_EDGES_MAX)
        g_csr[pos] = make_int2(c, __float_as_int(v));
}

// ---------------------------------------------------------------------------
// Build fp16 x0 = concat(user_emb, item_emb). One uint4 (8 halfs) per thread.
// ---------------------------------------------------------------------------
__global__ __launch_bounds__(256)
void copy_x0(const float4* __restrict__ user_emb,
             const float4* __restrict__ item_emb) {
    const int total = N_NODES * ROW_U4;
    for (int i = blockIdx.x * blockDim.x + threadIdx.x; i < total;
         i += gridDim.x * blockDim.x) {
        int f4 = i * 2;                       // index into float4 concat space
        float4 a, b;
        if (f4 < N_USERS * 16) {
            a = user_emb[f4];
            b = user_emb[f4 + 1];
        } else {
            a = item_emb[f4 - N_USERS * 16];
            b = item_emb[f4 - N_USERS * 16 + 1];
        }
        uint4 u;
        u.x = f2h(a.x, a.y);
        u.y = f2h(a.z, a.w);
        u.z = f2h(b.x, b.y);
        u.w = f2h(b.z, b.w);
        g_x0h[i] = u;
    }
}

// ---------------------------------------------------------------------------
// fp16 CSR SpMM: y[row] = sum_j val_j * x[col_j]. 8 lanes per row; each lane
// owns 8 half columns (one uint4 = 16B gather per edge). f32 accumulators,
// single fp16 store per lane. FILTER=1: only rows the gather reads.
// ---------------------------------------------------------------------------
template <int FILTER>
__global__ __launch_bounds__(256)
void spmm_h(const uint4* __restrict__ x, uint4* __restrict__ y) {
    int gid = blockIdx.x * blockDim.x + threadIdx.x;
    int row = gid >> 3;
    int c   = gid & 7;
    if (row >= N_NODES) return;
    if (FILTER) {
        if (!((g_bitmap[row >> 5] >> (row & 31)) & 1u)) return;
    }

    int beg = g_rowptr[row];
    int end = g_rowptr[row + 1];

    float a0 = 0.f, a1 = 0.f, a2 = 0.f, a3 = 0.f;
    float a4 = 0.f, a5 = 0.f, a6 = 0.f, a7 = 0.f;

    #pragma unroll 4
    for (int j = beg; j < end; j++) {
        int2  cv = __ldcs(&g_csr[j]);          // evict-first: keep x in L2
        float v  = __int_as_float(cv.y);
        uint4 u  = __ldg(&x[(size_t)cv.x * ROW_U4 + c]);
        float2 f0 = h2f(u.x), f1 = h2f(u.y), f2 = h2f(u.z), f3 = h2f(u.w);
        a0 = fmaf(v, f0.x, a0);  a1 = fmaf(v, f0.y, a1);
        a2 = fmaf(v, f1.x, a2);  a3 = fmaf(v, f1.y, a3);
        a4 = fmaf(v, f2.x, a4);  a5 = fmaf(v, f2.y, a5);
        a6 = fmaf(v, f3.x, a6);  a7 = fmaf(v, f3.y, a7);
    }

    uint4 o;
    o.x = f2h(a0, a1);
    o.y = f2h(a2, a3);
    o.z = f2h(a4, a5);
    o.w = f2h(a6, a7);
    y[(size_t)row * ROW_U4 + c] = o;
}

// ---------------------------------------------------------------------------
// Final gather: 0.25*(ego_f32 + L1 + L2 + L3) at the requested rows + raw
// f32 gathers. 16 lanes per sample; each lane: 4 floats = 2 half2 per layer.
// out layout: [6][BATCH][EMB] f32 contiguous.
// ---------------------------------------------------------------------------
__global__ __launch_bounds__(256)
void gather_kernel(const int* __restrict__ users,
                   const int* __restrict__ pos,
                   const int* __restrict__ neg,
                   const float4* __restrict__ user_emb,
                   const float4* __restrict__ item_emb,
                   float4* __restrict__ out) {
    int gid = blockIdx.x * blockDim.x + threadIdx.x;
    int i = gid >> 4;
    int c = gid & 15;          // float4 column 0..15
    if (i >= BATCH) return;

    const uint2* l1 = (const uint2*)g_l1h;
    const uint2* l2 = (const uint2*)g_l2h;
    const uint2* l3 = (const uint2*)g_l3h;
    // per row: 16 uint2 (each uint2 = 4 halfs = one float4's worth)

    int idxs[3];
    idxs[0] = users[i];
    idxs[1] = N_USERS + pos[i];
    idxs[2] = N_USERS + neg[i];

    const float a = 0.25f;

    #pragma unroll
    for (int k = 0; k < 3; k++) {
        int node = idxs[k];
        float4 ego = (node < N_USERS)
                   ? user_emb[node * 16 + c]
                   : item_emb[(node - N_USERS) * 16 + c];

        size_t off = (size_t)node * 16 + c;
        uint2 u1 = l1[off], u2 = l2[off], u3 = l3[off];
        float2 p1a = h2f(u1.x), p1b = h2f(u1.y);
        float2 p2a = h2f(u2.x), p2b = h2f(u2.y);
        float2 p3a = h2f(u3.x), p3b = h2f(u3.y);

        float4 f;
        f.x = a * (ego.x + p1a.x + p2a.x + p3a.x);
        f.y = a * (ego.y + p1a.y + p2a.y + p3a.y);
        f.z = a * (ego.z + p1b.x + p2b.x + p3b.x);
        f.w = a * (ego.w + p1b.y + p2b.y + p3b.y);

        out[((size_t)k * BATCH + i) * 16 + c] = f;          // final rows
        out[((size_t)(k + 3) * BATCH + i) * 16 + c] = ego;  // ego rows
    }
}

// ---------------------------------------------------------------------------
extern "C" void kernel_launch(void* const* d_in, const int* in_sizes, int n_in,
                              void* d_out, int out_size) {
    const int*    adj_rows = (const int*)   d_in[0];
    const int*    adj_cols = (const int*)   d_in[1];
    const float*  adj_vals = (const float*) d_in[2];
    const int*    users    = (const int*)   d_in[3];
    const int*    pos      = (const int*)   d_in[4];
    const int*    neg      = (const int*)   d_in[5];
    const float4* user_emb = (const float4*)d_in[6];
    const float4* item_emb = (const float4*)d_in[7];
    float4*       out      = (float4*)      d_out;

    int n_edges = in_sizes[0];
    if (n_edges > N_EDGES_MAX) n_edges = N_EDGES_MAX;

    const int TPB = 256;

    // metadata
    zero_meta<<<(N_NODES + TPB - 1) / TPB, TPB>>>();
    set_bitmap<<<(3 * BATCH + TPB - 1) / TPB, TPB>>>(users, pos, neg);

    // CSR build
    int hgrid = ((n_edges >> 2) + TPB - 1) / TPB + 1;
    histogram<<<hgrid, TPB>>>(adj_rows, n_edges);
    scan_pass1<<<SCAN_NB, SCAN_BT>>>();
    scan_pass2<<<1, 256>>>();
    scan_pass3<<<(N_NODES + TPB - 1) / TPB, TPB>>>();
    scatter_csr<<<(n_edges + TPB - 1) / TPB, TPB>>>(adj_rows, adj_cols, adj_vals, n_edges);

    // fp16 x0 concat
    copy_x0<<<2048, TPB>>>(user_emb, item_emb);

    // three propagation layers, atomic-free, fp16 storage / f32 accum
    {
        int sgrid = (N_NODES * 8 + TPB - 1) / TPB;
        void* px0; void* pl1; void* pl2; void* pl3;
        cudaGetSymbolAddress(&px0, g_x0h);
        cudaGetSymbolAddress(&pl1, g_l1h);
        cudaGetSymbolAddress(&pl2, g_l2h);
        cudaGetSymbolAddress(&pl3, g_l3h);
        spmm_h<0><<<sgrid, TPB>>>((const uint4*)px0, (uint4*)pl1);
        spmm_h<0><<<sgrid, TPB>>>((const uint4*)pl1, (uint4*)pl2);
        spmm_h<1><<<sgrid, TPB>>>((const uint4*)pl2, (uint4*)pl3);
    }

    // outputs
    gather_kernel<<<(BATCH * 16 + TPB - 1) / TPB, TPB>>>(users, pos, neg,
                                                         user_emb, item_emb, out);
}